// round 1
// baseline (speedup 1.0000x reference)
#include <cuda_runtime.h>
#include <math.h>
#include <math_constants.h>

#define B_  2
#define T_  2048
#define C_  1024
#define H_  16
#define D_  64

// Scratch (allocation-free rule: __device__ globals)
static __device__ float g_q[(size_t)B_*H_*T_*D_];
static __device__ float g_k[(size_t)B_*H_*T_*D_];
static __device__ float g_v[(size_t)B_*H_*T_*D_];
static __device__ float g_y[(size_t)B_*T_*C_];
static __device__ float g_bias[H_*T_];     // bias per (head, distance)
static __device__ float g_cos[T_*D_];
static __device__ float g_sin[T_*D_];

// ---------------------------------------------------------------------------
// Tables: rotary cos/sin [T, D] and relative-position bias per distance [H, T]
// ---------------------------------------------------------------------------
__global__ void tables_kernel(const float* __restrict__ rel_table) {
    int idx = blockIdx.x * blockDim.x + threadIdx.x;
    if (idx < T_ * D_) {
        int t = idx >> 6;
        int d = idx & 63;
        int j = d & 31;                       // freqs duplicated across halves
        float inv = (float)pow(10000.0, -(double)(2 * j) / 64.0);
        float fr = (float)t * inv;
        g_cos[idx] = cosf(fr);
        g_sin[idx] = sinf(fr);
    }
    if (idx < H_ * T_) {
        int h = idx / T_;
        int n = idx % T_;                     // distance = q_pos - k_pos >= 0
        int bucket;
        if (n < 16) {
            bucket = n;
        } else {
            float v = logf((float)n * (1.0f / 16.0f)) / 2.0794415416798357f * 16.0f;
            bucket = 16 + (int)v;             // trunc toward zero, v >= 0
            if (bucket > 31) bucket = 31;
        }
        g_bias[idx] = rel_table[bucket * H_ + h];
    }
}

// ---------------------------------------------------------------------------
// 128x128x16 tiled SGEMM body. M=B*T=4096, N=K=C=1024 fixed.
// mode 0: out[m*N+n]  (row-major [B*T, C])
// mode 1: out in head layout [B,H,T,D]
// ---------------------------------------------------------------------------
__device__ __forceinline__ void gemm_body(const float* __restrict__ A,
                                          const float* __restrict__ W,
                                          const float* __restrict__ bias,
                                          float* __restrict__ out,
                                          int mode) {
    __shared__ float As[16][128];
    __shared__ float Ws[16][132];

    const int K = C_, N = C_;
    int tid = threadIdx.x;
    int bm = blockIdx.y * 128;
    int bn = blockIdx.x * 128;
    int ty = tid >> 4;     // 0..15
    int tx = tid & 15;     // 0..15

    float acc[8][8];
#pragma unroll
    for (int i = 0; i < 8; i++)
#pragma unroll
        for (int j = 0; j < 8; j++) acc[i][j] = 0.f;

    int arow = tid >> 2;            // 0..63
    int ac4  = (tid & 3) << 2;      // 0,4,8,12
    int wrow = tid >> 5;            // 0..7
    int wc4  = (tid & 31) << 2;     // 0..124

    for (int k0 = 0; k0 < K; k0 += 16) {
        float4 a0 = *(const float4*)(A + (size_t)(bm + arow) * K + k0 + ac4);
        float4 a1 = *(const float4*)(A + (size_t)(bm + arow + 64) * K + k0 + ac4);
        float4 w0 = *(const float4*)(W + (size_t)(k0 + wrow) * N + bn + wc4);
        float4 w1 = *(const float4*)(W + (size_t)(k0 + wrow + 8) * N + bn + wc4);

        __syncthreads();
        As[ac4 + 0][arow] = a0.x; As[ac4 + 1][arow] = a0.y;
        As[ac4 + 2][arow] = a0.z; As[ac4 + 3][arow] = a0.w;
        As[ac4 + 0][arow + 64] = a1.x; As[ac4 + 1][arow + 64] = a1.y;
        As[ac4 + 2][arow + 64] = a1.z; As[ac4 + 3][arow + 64] = a1.w;
        *(float4*)&Ws[wrow][wc4]     = w0;
        *(float4*)&Ws[wrow + 8][wc4] = w1;
        __syncthreads();

#pragma unroll
        for (int kk = 0; kk < 16; kk++) {
            float ar[8], br[8];
#pragma unroll
            for (int i = 0; i < 8; i++) ar[i] = As[kk][ty * 8 + i];
#pragma unroll
            for (int j = 0; j < 8; j++) br[j] = Ws[kk][tx * 8 + j];
#pragma unroll
            for (int i = 0; i < 8; i++)
#pragma unroll
                for (int j = 0; j < 8; j++) acc[i][j] += ar[i] * br[j];
        }
    }

    int gcol0 = bn + tx * 8;
    if (mode == 0) {
#pragma unroll
        for (int i = 0; i < 8; i++) {
            int grow = bm + ty * 8 + i;
            float* op = out + (size_t)grow * N + gcol0;
#pragma unroll
            for (int j = 0; j < 8; j++) op[j] = acc[i][j] + bias[gcol0 + j];
        }
    } else {
        int h  = gcol0 >> 6;
        int d0 = gcol0 & 63;
#pragma unroll
        for (int i = 0; i < 8; i++) {
            int grow = bm + ty * 8 + i;
            int b = grow >> 11;
            int t = grow & (T_ - 1);
            float* dp = out + (((size_t)b * H_ + h) * T_ + t) * D_ + d0;
#pragma unroll
            for (int j = 0; j < 8; j++) dp[j] = acc[i][j] + bias[gcol0 + j];
        }
    }
}

__global__ __launch_bounds__(256) void qkv_gemm_kernel(
        const float* __restrict__ x,
        const float* __restrict__ Wq, const float* __restrict__ bq,
        const float* __restrict__ Wk, const float* __restrict__ bk,
        const float* __restrict__ Wv, const float* __restrict__ bv) {
    const float* W; const float* bias; float* dst;
    int z = blockIdx.z;
    if (z == 0)      { W = Wq; bias = bq; dst = g_q; }
    else if (z == 1) { W = Wk; bias = bk; dst = g_k; }
    else             { W = Wv; bias = bv; dst = g_v; }
    gemm_body(x, W, bias, dst, 1);
}

__global__ __launch_bounds__(256) void proj_gemm_kernel(
        const float* __restrict__ Wp, const float* __restrict__ bp,
        float* __restrict__ out) {
    gemm_body(g_y, Wp, bp, out, 0);
}

// ---------------------------------------------------------------------------
// Rotary: each thread handles the (d, d+32) pair -> no cross-thread race.
// ---------------------------------------------------------------------------
__global__ void rope_kernel() {
    const int NH = B_ * H_ * T_ * 32;
    int idx = blockIdx.x * blockDim.x + threadIdx.x;
    float* arr = g_q;
    if (idx >= NH) { arr = g_k; idx -= NH; }
    if (idx >= NH) return;
    int d = idx & 31;
    int row = idx >> 5;                 // (b*H+h)*T + t
    int t = row & (T_ - 1);
    float c = g_cos[(t << 6) + d];
    float s = g_sin[(t << 6) + d];
    size_t p = ((size_t)row << 6) + d;
    float x1 = arr[p], x2 = arr[p + 32];
    arr[p]      = x1 * c - x2 * s;
    arr[p + 32] = x2 * c + x1 * s;
}

// ---------------------------------------------------------------------------
// Flash-style causal attention. 64 queries / CTA, 1 query / thread.
// ---------------------------------------------------------------------------
__global__ __launch_bounds__(64) void attn_kernel() {
    __shared__ float Ks[64 * 64];
    __shared__ float Vs[64 * 64];
    __shared__ float Bsb[T_];

    int bh = blockIdx.y;                  // b*H + h
    int h = bh & (H_ - 1);
    int qb = gridDim.x - 1 - blockIdx.x;  // big-work CTAs launch first
    int q0 = qb << 6;
    int tid = threadIdx.x;

    const float* qptr  = g_q + ((size_t)bh * T_ + q0) * D_;
    const float* kbase = g_k + (size_t)bh * T_ * D_;
    const float* vbase = g_v + (size_t)bh * T_ * D_;

    {   // stage bias row + Q tile (Q temporarily in Ks)
        const float4* b4 = (const float4*)(g_bias + h * T_);
        for (int i = tid; i < T_ / 4; i += 64) ((float4*)Bsb)[i] = b4[i];
        const float4* q4 = (const float4*)qptr;
        for (int i = tid; i < 64 * 64 / 4; i += 64) ((float4*)Ks)[i] = q4[i];
    }
    __syncthreads();

    float qreg[64];
#pragma unroll
    for (int d = 0; d < 64; d++) qreg[d] = Ks[tid * 64 + d];

    int qi = q0 + tid;
    float mval = -CUDART_INF_F;
    float lval = 0.f;
    float acc[64];
#pragma unroll
    for (int d = 0; d < 64; d++) acc[d] = 0.f;

    for (int j0 = 0; j0 <= q0; j0 += 64) {
        __syncthreads();
        const float4* k4 = (const float4*)(kbase + (size_t)j0 * D_);
        const float4* v4 = (const float4*)(vbase + (size_t)j0 * D_);
        for (int i = tid; i < 1024; i += 64) {
            ((float4*)Ks)[i] = k4[i];
            ((float4*)Vs)[i] = v4[i];
        }
        __syncthreads();

        int jmax = qi - j0 + 1;
        if (jmax > 64) jmax = 64;
        for (int j = 0; j < jmax; j++) {
            const float* kr = Ks + j * 64;
            float s = 0.f;
#pragma unroll
            for (int d = 0; d < 64; d++) s += qreg[d] * kr[d];
            s = (s + Bsb[qi - j0 - j]) * 0.125f;   // 1/sqrt(64)

            const float* vr = Vs + j * 64;
            if (s > mval) {
                float corr = __expf(mval - s);     // exp(-inf)=0 on first hit
                mval = s;
                lval = lval * corr + 1.f;
#pragma unroll
                for (int d = 0; d < 64; d++) acc[d] = acc[d] * corr + vr[d];
            } else {
                float p = __expf(s - mval);
                lval += p;
#pragma unroll
                for (int d = 0; d < 64; d++) acc[d] += p * vr[d];
            }
        }
    }

    float inv = 1.f / lval;
    int b = bh >> 4;
    float* yo = g_y + ((size_t)b * T_ + qi) * C_ + h * D_;
#pragma unroll
    for (int d4 = 0; d4 < 16; d4++) {
        float4 o;
        o.x = acc[d4 * 4 + 0] * inv;
        o.y = acc[d4 * 4 + 1] * inv;
        o.z = acc[d4 * 4 + 2] * inv;
        o.w = acc[d4 * 4 + 3] * inv;
        ((float4*)yo)[d4] = o;
    }
}

// ---------------------------------------------------------------------------
extern "C" void kernel_launch(void* const* d_in, const int* in_sizes, int n_in,
                              void* d_out, int out_size) {
    const float* x   = (const float*)d_in[0];
    const float* Wq  = (const float*)d_in[1];
    const float* bq  = (const float*)d_in[2];
    const float* Wk  = (const float*)d_in[3];
    const float* bk  = (const float*)d_in[4];
    const float* Wv  = (const float*)d_in[5];
    const float* bv  = (const float*)d_in[6];
    const float* Wp  = (const float*)d_in[7];
    const float* bp  = (const float*)d_in[8];
    const float* tbl = (const float*)d_in[9];
    float* out = (float*)d_out;

    tables_kernel<<<(T_ * D_ + 255) / 256, 256>>>(tbl);

    dim3 ggrid(C_ / 128, (B_ * T_) / 128, 3);
    qkv_gemm_kernel<<<ggrid, 256>>>(x, Wq, bq, Wk, bk, Wv, bv);

    int rope_threads = 2 * B_ * H_ * T_ * 32;
    rope_kernel<<<(rope_threads + 255) / 256, 256>>>();

    attn_kernel<<<dim3(T_ / 64, B_ * H_), 64>>>();

    proj_gemm_kernel<<<dim3(C_ / 128, (B_ * T_) / 128), 256>>>(Wp, bp, out);
}